// round 13
// baseline (speedup 1.0000x reference)
#include <cuda_runtime.h>
#include <cuda_bf16.h>

// ---------------------------------------------------------------------------
// GAT-style sparse attention, CSR-fused formulation.  5 launches:
//   csr(1,s0)  scatter(2,s0)  qkv_a(3,s1)  qkv_b(4,s1 <- profiled)  agg(5,s0)
// agg: 4 nodes/warp, 8-lane group per node, 4-edge unroll, int4 index loads
// (CSR rows padded to multiples of 4 for aligned vector index loads).
// edge_index arrives as int32.  Plain sm_103 target: mma.sync/ldmatrix only.
// ---------------------------------------------------------------------------

#define IN_DIM 256
#define HD 32
#define NMAX 100000
#define EMAX 1600000
#define EMAX_PAD 1900032          // E + 3*N headroom for row padding
#define SCAN_BLK 1024

__device__ __align__(16) float g_Q[NMAX * HD];
__device__ __align__(16) float g_KV[NMAX * 64];   // per node: K[0:32) | V[32:64)
__device__ int g_cnt[NMAX];       // zero at load; agg re-zeros for next call
__device__ int g_rowptr[NMAX];    // padded row starts (multiples of 4)
__device__ int g_cursor[NMAX];
__device__ __align__(16) int g_sdst[EMAX_PAD];
__device__ int g_bsum[128];
// csr_kernel sync state (all zero at load; self-resetting each run)
__device__ int g_bar1, g_rel1, g_done1;
__device__ int g_ready[128];

// ---------------------------------------------------------------------------
// helpers
// ---------------------------------------------------------------------------
__device__ __forceinline__ unsigned smem_u32(const void* p)
{
    unsigned a;
    asm("{ .reg .u64 t; cvta.to.shared.u64 t, %1; cvt.u32.u64 %0, t; }"
        : "=r"(a) : "l"(p));
    return a;
}
__device__ __forceinline__ unsigned short bf16h(float x)
{
    return __bfloat16_as_ushort(__float2bfloat16(x));
}
__device__ __forceinline__ float bf16f(unsigned short u)
{
    return __bfloat162float(__ushort_as_bfloat16(u));
}

__device__ __forceinline__ void ldsm_x4(unsigned r[4], unsigned addr)
{
    asm volatile("ldmatrix.sync.aligned.m8n8.x4.shared.b16 {%0,%1,%2,%3}, [%4];"
                 : "=r"(r[0]), "=r"(r[1]), "=r"(r[2]), "=r"(r[3]) : "r"(addr));
}
__device__ __forceinline__ void ldsm_x2(unsigned r[2], unsigned addr)
{
    asm volatile("ldmatrix.sync.aligned.m8n8.x2.shared.b16 {%0,%1}, [%2];"
                 : "=r"(r[0]), "=r"(r[1]) : "r"(addr));
}
__device__ __forceinline__ void mma_bf16(float c[4], const unsigned a[4],
                                         const unsigned b[2])
{
    asm volatile("mma.sync.aligned.m16n8k16.row.col.f32.bf16.bf16.f32 "
                 "{%0,%1,%2,%3}, {%4,%5,%6,%7}, {%8,%9}, {%0,%1,%2,%3};"
                 : "+f"(c[0]), "+f"(c[1]), "+f"(c[2]), "+f"(c[3])
                 : "r"(a[0]), "r"(a[1]), "r"(a[2]), "r"(a[3]),
                   "r"(b[0]), "r"(b[1]));
}

// ---------------------------------------------------------------------------
// QKV GEMM via mma.sync bf16 hi/lo, software-pipelined X staging,
// per-chunk B built inline from W.  n0_base allows split launches.
// ---------------------------------------------------------------------------
#define ASTRIDE 72
#define SM_AH 0
#define SM_AL 18432
#define SM_BH 36864
#define SM_BL 50688
#define QKV_SMEM 64512

__global__ void __launch_bounds__(256, 1)
qkv_mma_kernel(const float* __restrict__ X,
               const float* __restrict__ Wq,
               const float* __restrict__ Wk,
               const float* __restrict__ Wv,
               int N, int n0_base)
{
    extern __shared__ char smem[];
    const unsigned sb = smem_u32(smem);
    const int tid  = threadIdx.x;
    const int wid  = tid >> 5;
    const int lane = tid & 31;
    const int n0   = n0_base + blockIdx.x * 128;

    float acc[12][4];
    #pragma unroll
    for (int j = 0; j < 12; j++)
        #pragma unroll
        for (int i = 0; i < 4; i++) acc[j][i] = 0.f;

    const int a_row = (lane & 15);
    const int a_kh  = ((lane >> 4) & 1) * 8;
    const int b_row = (lane & 7);
    const int b_kh  = ((lane >> 3) & 1) * 8;

    float4 xv[8];
    #pragma unroll
    for (int ii = 0; ii < 8; ii++) {
        int q = tid + 256 * ii;
        int r = q >> 4, j4 = q & 15;
        int node = n0 + r;
        xv[ii] = (node < N)
            ? *(const float4*)&X[(size_t)node * IN_DIM + 4 * j4]
            : make_float4(0.f, 0.f, 0.f, 0.f);
    }

    for (int c = 0; c < 4; c++) {
        __syncthreads();

        // Stage A chunk c (hi/lo bf16) from prefetched registers
        #pragma unroll
        for (int ii = 0; ii < 8; ii++) {
            int q = tid + 256 * ii;
            int r = q >> 4, j4 = q & 15;
            float4 v = xv[ii];
            unsigned short hx = bf16h(v.x), hy = bf16h(v.y),
                           hz = bf16h(v.z), hw = bf16h(v.w);
            unsigned short lx = bf16h(v.x - bf16f(hx)), ly = bf16h(v.y - bf16f(hy)),
                           lz = bf16h(v.z - bf16f(hz)), lw = bf16h(v.w - bf16f(hw));
            unsigned byte = r * (ASTRIDE * 2) + 8 * j4;
            *(uint2*)(smem + SM_AH + byte) =
                make_uint2((unsigned)hx | ((unsigned)hy << 16),
                           (unsigned)hz | ((unsigned)hw << 16));
            *(uint2*)(smem + SM_AL + byte) =
                make_uint2((unsigned)lx | ((unsigned)ly << 16),
                           (unsigned)lz | ((unsigned)lw << 16));
        }

        // Build B chunk c inline from W: 3072 bf16-pairs (96 rows x 32 pairs)
        #pragma unroll
        for (int ii = 0; ii < 12; ii++) {
            int i  = tid + 256 * ii;          // 0..3071
            int n  = i % 96;
            int jp = i / 96;
            int k0 = c * 64 + 2 * jp;
            const float* Wm = (n < 32) ? Wq : (n < 64) ? Wk : Wv;
            float w0 = Wm[k0 * HD + (n & 31)];
            float w1 = Wm[(k0 + 1) * HD + (n & 31)];
            unsigned short h0 = bf16h(w0), h1 = bf16h(w1);
            unsigned short l0 = bf16h(w0 - bf16f(h0));
            unsigned short l1 = bf16h(w1 - bf16f(h1));
            unsigned byte = n * (ASTRIDE * 2) + 4 * jp;
            *(unsigned*)(smem + SM_BH + byte) = (unsigned)h0 | ((unsigned)h1 << 16);
            *(unsigned*)(smem + SM_BL + byte) = (unsigned)l0 | ((unsigned)l1 << 16);
        }
        __syncthreads();

        // Prefetch next chunk's X into registers (hidden under MMA compute)
        if (c < 3) {
            #pragma unroll
            for (int ii = 0; ii < 8; ii++) {
                int q = tid + 256 * ii;
                int r = q >> 4, j4 = q & 15;
                int node = n0 + r;
                xv[ii] = (node < N)
                    ? *(const float4*)&X[(size_t)node * IN_DIM + (c + 1) * 64 + 4 * j4]
                    : make_float4(0.f, 0.f, 0.f, 0.f);
            }
        }

        #pragma unroll
        for (int ks = 0; ks < 4; ks++) {
            unsigned ah[4], al[4];
            {
                unsigned byte = (wid * 16 + a_row) * (ASTRIDE * 2)
                              + (ks * 16 + a_kh) * 2;
                ldsm_x4(ah, sb + SM_AH + byte);
                ldsm_x4(al, sb + SM_AL + byte);
            }
            #pragma unroll
            for (int j = 0; j < 12; j++) {
                unsigned bh[2], bl[2];
                unsigned byte = (j * 8 + b_row) * (ASTRIDE * 2)
                              + (ks * 16 + b_kh) * 2;
                ldsm_x2(bh, sb + SM_BH + byte);
                ldsm_x2(bl, sb + SM_BL + byte);
                mma_bf16(acc[j], ah, bh);
                mma_bf16(acc[j], ah, bl);
                mma_bf16(acc[j], al, bh);
            }
        }
    }

    // Epilogue: Q separate; K/V interleaved per node (64-float row)
    const int g  = lane >> 2;
    const int tt = lane & 3;
    const int row_hi = n0 + wid * 16 + g;
    const int row_lo = row_hi + 8;
    #pragma unroll
    for (int j = 0; j < 12; j++) {
        int col = 8 * (j & 3) + 2 * tt;
        float* p_hi;
        float* p_lo;
        if (j < 4) {
            p_hi = &g_Q[(size_t)row_hi * HD + col];
            p_lo = &g_Q[(size_t)row_lo * HD + col];
        } else if (j < 8) {
            p_hi = &g_KV[(size_t)row_hi * 64 + col];
            p_lo = &g_KV[(size_t)row_lo * 64 + col];
        } else {
            p_hi = &g_KV[(size_t)row_hi * 64 + 32 + col];
            p_lo = &g_KV[(size_t)row_lo * 64 + 32 + col];
        }
        if (row_hi < N) *(float2*)p_hi = make_float2(acc[j][0], acc[j][1]);
        if (row_lo < N) *(float2*)p_lo = make_float2(acc[j][2], acc[j][3]);
    }
}

// ---------------------------------------------------------------------------
// CSR hist + scan in ONE kernel (grid-barrier; state self-resets).
// Row lengths padded to multiples of 4 so row starts are 16B-aligned.
// ---------------------------------------------------------------------------
__global__ void __launch_bounds__(SCAN_BLK)
csr_kernel(const int* __restrict__ ei, int E, int N, int nb)
{
    __shared__ int wsum[32];
    __shared__ int sh2[128];
    __shared__ int s_boff;

    const int t    = threadIdx.x;
    const int lane = t & 31;
    const int wid  = t >> 5;
    const int b    = blockIdx.x;
    const int gtid = b * SCAN_BLK + t;
    const int gsz  = nb * SCAN_BLK;

    // ---- phase 1: histogram (int4 grid-stride) ----
    const int nquad = E >> 2;
    for (int q = gtid; q < nquad; q += gsz) {
        int4 s = ((const int4*)ei)[q];
        atomicAdd(&g_cnt[s.x], 1);
        atomicAdd(&g_cnt[s.y], 1);
        atomicAdd(&g_cnt[s.z], 1);
        atomicAdd(&g_cnt[s.w], 1);
    }
    for (int e = (nquad << 2) + gtid; e < E; e += gsz)
        atomicAdd(&g_cnt[ei[e]], 1);

    // ---- grid barrier ----
    __syncthreads();
    if (t == 0) {
        __threadfence();
        int ticket = atomicAdd(&g_bar1, 1);
        if (ticket == nb - 1) atomicExch(&g_rel1, 1);
        while (atomicAdd(&g_rel1, 0) == 0) {}
        __threadfence();
    }
    __syncthreads();

    // ---- phase 2: block-local exclusive scan of PADDED counts ----
    const int i = gtid;
    int v = (i < N) ? ((g_cnt[i] + 3) & ~3) : 0;   // pad rows to multiple of 4
    int x = v;
    #pragma unroll
    for (int off = 1; off < 32; off <<= 1) {
        int y = __shfl_up_sync(0xffffffffu, x, off);
        if (lane >= off) x += y;
    }
    if (lane == 31) wsum[wid] = x;
    __syncthreads();
    if (wid == 0) {
        int s = wsum[lane];
        #pragma unroll
        for (int off = 1; off < 32; off <<= 1) {
            int y = __shfl_up_sync(0xffffffffu, s, off);
            if (lane >= off) s += y;
        }
        wsum[lane] = s;
    }
    __syncthreads();
    const int base = (wid > 0) ? wsum[wid - 1] : 0;
    const int excl = base + x - v;

    if (t == SCAN_BLK - 1) {
        g_bsum[b] = base + x;
        __threadfence();
        atomicExch(&g_ready[b], 1);
    }

    int val = 0;
    if (t < nb) {
        while (atomicAdd(&g_ready[t], 0) == 0) {}
        __threadfence();
        val = g_bsum[t];
    }
    if (t < 128) sh2[t] = (t < nb) ? val : 0;
    __syncthreads();
    #pragma unroll
    for (int off = 1; off < 128; off <<= 1) {
        int y = (t < 128 && t >= off) ? sh2[t - off] : 0;
        __syncthreads();
        if (t < 128) sh2[t] += y;
        __syncthreads();
    }
    if (t == b) s_boff = sh2[b] - val;
    __syncthreads();

    if (i < N) {
        int rp = s_boff + excl;
        g_rowptr[i] = rp;
        g_cursor[i] = rp;
    }

    __syncthreads();
    if (t == 0) {
        int d = atomicAdd(&g_done1, 1);
        if (d == nb - 1) {
            for (int k = 0; k < nb; k++) g_ready[k] = 0;
            g_bar1 = 0;
            g_rel1 = 0;
            g_done1 = 0;
            __threadfence();
        }
    }
}

__global__ void scatter_kernel(const int* __restrict__ ei, int E)
{
    int b = (blockIdx.x * blockDim.x + threadIdx.x) * 4;
    if (b + 3 < E) {
        int4 s = *(const int4*)&ei[b];
        int4 d = *(const int4*)&ei[E + b];
        g_sdst[atomicAdd(&g_cursor[s.x], 1)] = d.x;
        g_sdst[atomicAdd(&g_cursor[s.y], 1)] = d.y;
        g_sdst[atomicAdd(&g_cursor[s.z], 1)] = d.z;
        g_sdst[atomicAdd(&g_cursor[s.w], 1)] = d.w;
    } else {
        for (int e = b; e < E; e++) {
            int s = ei[e];
            int d = ei[E + e];
            g_sdst[atomicAdd(&g_cursor[s], 1)] = d;
        }
    }
}

// ---------------------------------------------------------------------------
// Fused softmax + aggregate: 4 nodes/warp, 8-lane group per node,
// 4 edges per iteration via one aligned int4 index load (broadcast).
// Accumulator IS the output row (no epilogue reduction).
// ---------------------------------------------------------------------------
__global__ void __launch_bounds__(256)
agg_kernel(float* __restrict__ out, int N)
{
    const int lane = threadIdx.x & 31;
    const int warp = (blockIdx.x * blockDim.x + threadIdx.x) >> 5;
    const int grp  = lane >> 3;
    const int sub  = lane & 7;
    const int n    = warp * 4 + grp;
    const bool nvalid = (n < N);
    const int nn   = nvalid ? n : 0;

    const float4 q4 = *(const float4*)&g_Q[(size_t)nn * HD + sub * 4];
    const int rs  = g_rowptr[nn];                 // multiple of 4 -> 16B aligned
    const int cnt = nvalid ? g_cnt[nn] : 0;

    int nit = (cnt + 3) >> 2;
    nit = max(nit, __shfl_xor_sync(0xffffffffu, nit, 8));
    nit = max(nit, __shfl_xor_sync(0xffffffffu, nit, 16));

    float4 acc = make_float4(0.f, 0.f, 0.f, 0.f);
    float  sw  = 0.f;

    int4 idx = (0 < cnt) ? *(const int4*)&g_sdst[rs] : make_int4(0, 0, 0, 0);

    for (int it = 0; it < nit; it++) {
        const int e0 = it * 4;
        const bool v0 = (e0 < cnt), v1 = (e0 + 1 < cnt),
                   v2 = (e0 + 2 < cnt), v3 = (e0 + 3 < cnt);
        const int d0 = v0 ? idx.x : 0;
        const int d1 = v1 ? idx.y : 0;
        const int d2 = v2 ? idx.z : 0;
        const int d3 = v3 ? idx.w : 0;

        // 8 gathers in flight (clamped indices are safe; w=0 kills them)
        const float* kv0 = &g_KV[(size_t)d0 * 64];
        const float* kv1 = &g_KV[(size_t)d1 * 64];
        const float* kv2 = &g_KV[(size_t)d2 * 64];
        const float* kv3 = &g_KV[(size_t)d3 * 64];
        const float4 k0 = *(const float4*)&kv0[sub * 4];
        const float4 k1 = *(const float4*)&kv1[sub * 4];
        const float4 k2 = *(const float4*)&kv2[sub * 4];
        const float4 k3 = *(const float4*)&kv3[sub * 4];
        const float4 u0 = *(const float4*)&kv0[32 + sub * 4];
        const float4 u1 = *(const float4*)&kv1[32 + sub * 4];
        const float4 u2 = *(const float4*)&kv2[32 + sub * 4];
        const float4 u3 = *(const float4*)&kv3[32 + sub * 4];

        // prefetch next iteration's indices under the gather latency
        if (it + 1 < nit)
            idx = *(const int4*)&g_sdst[rs + (it + 1) * 4];

        float p0 = q4.x * k0.x + q4.y * k0.y + q4.z * k0.z + q4.w * k0.w;
        float p1 = q4.x * k1.x + q4.y * k1.y + q4.z * k1.z + q4.w * k1.w;
        float p2 = q4.x * k2.x + q4.y * k2.y + q4.z * k2.z + q4.w * k2.w;
        float p3 = q4.x * k3.x + q4.y * k3.y + q4.z * k3.z + q4.w * k3.w;
        #pragma unroll
        for (int off = 1; off <= 4; off <<= 1) {
            p0 += __shfl_xor_sync(0xffffffffu, p0, off);
            p1 += __shfl_xor_sync(0xffffffffu, p1, off);
            p2 += __shfl_xor_sync(0xffffffffu, p2, off);
            p3 += __shfl_xor_sync(0xffffffffu, p3, off);
        }

        const float w0 = v0 ? __expf(p0 * 0.17677669529663687f) : 0.f;
        const float w1 = v1 ? __expf(p1 * 0.17677669529663687f) : 0.f;
        const float w2 = v2 ? __expf(p2 * 0.17677669529663687f) : 0.f;
        const float w3 = v3 ? __expf(p3 * 0.17677669529663687f) : 0.f;
        sw += (w0 + w1) + (w2 + w3);

        acc.x += w0 * u0.x + w1 * u1.x + w2 * u2.x + w3 * u3.x;
        acc.y += w0 * u0.y + w1 * u1.y + w2 * u2.y + w3 * u3.y;
        acc.z += w0 * u0.z + w1 * u1.z + w2 * u2.z + w3 * u3.z;
        acc.w += w0 * u0.w + w1 * u1.w + w2 * u2.w + w3 * u3.w;
    }

    if (nvalid) {
        if (sub == 0) g_cnt[n] = 0;    // reset for next call's histogram
        float inv = (sw > 0.f) ? (1.f / sw) : 0.f;
        float4 o = make_float4(acc.x * inv, acc.y * inv, acc.z * inv, acc.w * inv);
        *(float4*)&out[(size_t)n * HD + sub * 4] = o;
    }
}

// ---------------------------------------------------------------------------
// Launch: 5 kernels, fork-join across two streams.
//   csr(1,s0)  scatter(2,s0)  qkv_a(3,s1)  qkv_b(4,s1 <- profiled)  agg(5,s0)
// ---------------------------------------------------------------------------
extern "C" void kernel_launch(void* const* d_in, const int* in_sizes, int n_in,
                              void* d_out, int out_size)
{
    const float* X  = (const float*)d_in[0];
    const int*   ei = (const int*)d_in[1];     // int32 edge indices
    const float* Wq = (const float*)d_in[2];
    const float* Wk = (const float*)d_in[3];
    const float* Wv = (const float*)d_in[4];
    float* out = (float*)d_out;

    const int N = in_sizes[0] / IN_DIM;
    const int E = in_sizes[1] / 2;
    const int nb = (N + SCAN_BLK - 1) / SCAN_BLK;   // 98 for N=100000 (<=128)

    // qkv split into two halves (for per-kernel profiling visibility)
    const int nb1   = ((N / 2) + 127) / 128;
    const int base2 = nb1 * 128;
    const int nb2   = (N - base2 + 127) / 128;

    static cudaStream_t s1 = nullptr;
    static cudaEvent_t  evF = nullptr, evA = nullptr;
    if (!s1) {
        cudaFuncSetAttribute(qkv_mma_kernel,
                             cudaFuncAttributeMaxDynamicSharedMemorySize,
                             QKV_SMEM);
        cudaStreamCreateWithFlags(&s1, cudaStreamNonBlocking);
        cudaEventCreateWithFlags(&evF, cudaEventDisableTiming);
        cudaEventCreateWithFlags(&evA, cudaEventDisableTiming);
    }

    // Fork
    cudaEventRecord(evF, 0);
    cudaStreamWaitEvent(s1, evF, 0);

    csr_kernel<<<nb, SCAN_BLK>>>(ei, E, N, nb);                          // 1
    scatter_kernel<<<(E / 4 + 255) / 256, 256>>>(ei, E);                 // 2
    qkv_mma_kernel<<<nb1, 256, QKV_SMEM, s1>>>(X, Wq, Wk, Wv, N, 0);     // 3
    qkv_mma_kernel<<<nb2, 256, QKV_SMEM, s1>>>(X, Wq, Wk, Wv, N, base2); // 4 <- profiled
    cudaEventRecord(evA, s1);

    // Join
    cudaStreamWaitEvent(0, evA, 0);
    agg_kernel<<<((N * 8) + 255) / 256, 256>>>(out, N);                  // 5
}

// round 14
// speedup vs baseline: 1.1242x; 1.1242x over previous
#include <cuda_runtime.h>
#include <cuda_bf16.h>

// ---------------------------------------------------------------------------
// GAT-style sparse attention, CSR-fused formulation.  5 launches:
//   csr(1,s0)  scatter(2,s0)  bprep(3,s1)  qkv(4,s1 <- profiled)  agg(5,s0)
// qkv: mma.sync bf16 hi/lo, cp.async-staged X and B, 2 CTAs/SM.
// agg: 4 nodes/warp, 8-lane group per node, 2-edge unroll (R12, measured).
// edge_index arrives as int32.  Plain sm_103 target: mma.sync/ldmatrix/cp.async.
// ---------------------------------------------------------------------------

#define IN_DIM 256
#define HD 32
#define NMAX 100000
#define EMAX 1600000
#define SCAN_BLK 1024

__device__ __align__(16) float g_Q[NMAX * HD];
__device__ __align__(16) float g_KV[NMAX * 64];   // per node: K[0:32) | V[32:64)
__device__ int g_cnt[NMAX];       // zero at load; agg re-zeros for next call
__device__ int g_rowptr[NMAX];
__device__ int g_cursor[NMAX];
__device__ __align__(16) int g_sdst[EMAX];
__device__ int g_bsum[128];
// csr_kernel sync state (all zero at load; self-resetting each run)
__device__ int g_bar1, g_rel1, g_done1;
__device__ int g_ready[128];
// Pre-built bf16 hi/lo of B=W^T in padded smem layout:
// [4 chunks][96 rows][36 uints] (144B rows; last 16B padding, never read)
__device__ __align__(16) unsigned g_Bhp[4 * 96 * 36];
__device__ __align__(16) unsigned g_Blp[4 * 96 * 36];

// ---------------------------------------------------------------------------
// helpers
// ---------------------------------------------------------------------------
__device__ __forceinline__ unsigned smem_u32(const void* p)
{
    unsigned a;
    asm("{ .reg .u64 t; cvta.to.shared.u64 t, %1; cvt.u32.u64 %0, t; }"
        : "=r"(a) : "l"(p));
    return a;
}
__device__ __forceinline__ unsigned short bf16h(float x)
{
    return __bfloat16_as_ushort(__float2bfloat16(x));
}
__device__ __forceinline__ float bf16f(unsigned short u)
{
    return __bfloat162float(__ushort_as_bfloat16(u));
}

__device__ __forceinline__ void cp16(unsigned dst, const void* src, int srcsz)
{
    asm volatile("cp.async.cg.shared.global [%0], [%1], 16, %2;"
                 :: "r"(dst),
                    "l"(__cvta_generic_to_global(src)),
                    "r"(srcsz) : "memory");
}
#define CP_COMMIT() asm volatile("cp.async.commit_group;" ::: "memory")
#define CP_WAIT0()  asm volatile("cp.async.wait_group 0;" ::: "memory")

__device__ __forceinline__ void ldsm_x4(unsigned r[4], unsigned addr)
{
    asm volatile("ldmatrix.sync.aligned.m8n8.x4.shared.b16 {%0,%1,%2,%3}, [%4];"
                 : "=r"(r[0]), "=r"(r[1]), "=r"(r[2]), "=r"(r[3]) : "r"(addr));
}
__device__ __forceinline__ void ldsm_x2(unsigned r[2], unsigned addr)
{
    asm volatile("ldmatrix.sync.aligned.m8n8.x2.shared.b16 {%0,%1}, [%2];"
                 : "=r"(r[0]), "=r"(r[1]) : "r"(addr));
}
__device__ __forceinline__ void mma_bf16(float c[4], const unsigned a[4],
                                         const unsigned b[2])
{
    asm volatile("mma.sync.aligned.m16n8k16.row.col.f32.bf16.bf16.f32 "
                 "{%0,%1,%2,%3}, {%4,%5,%6,%7}, {%8,%9}, {%0,%1,%2,%3};"
                 : "+f"(c[0]), "+f"(c[1]), "+f"(c[2]), "+f"(c[3])
                 : "r"(a[0]), "r"(a[1]), "r"(a[2]), "r"(a[3]),
                   "r"(b[0]), "r"(b[1]));
}

// ---------------------------------------------------------------------------
// B prep: bf16 hi/lo of W^T in PADDED layout (144B rows, cp.async-copyable).
// Chunk c, row n (0..95), pair jp (0..31): uint index c*3456 + n*36 + jp.
// ---------------------------------------------------------------------------
__global__ void bprep_kernel(const float* __restrict__ Wq,
                             const float* __restrict__ Wk,
                             const float* __restrict__ Wv)
{
    for (int idx = threadIdx.x; idx < 12288; idx += blockDim.x) {
        int c   = idx / 3072;
        int rem = idx % 3072;
        int n   = rem / 32;
        int jp  = rem % 32;
        int k0  = c * 64 + 2 * jp;
        const float* Wm = (n < 32) ? Wq : (n < 64) ? Wk : Wv;
        float w0 = Wm[k0 * HD + (n & 31)];
        float w1 = Wm[(k0 + 1) * HD + (n & 31)];
        unsigned short h0 = bf16h(w0), h1 = bf16h(w1);
        unsigned short l0 = bf16h(w0 - bf16f(h0));
        unsigned short l1 = bf16h(w1 - bf16f(h1));
        int g = c * 3456 + n * 36 + jp;
        g_Bhp[g] = (unsigned)h0 | ((unsigned)h1 << 16);
        g_Blp[g] = (unsigned)l0 | ((unsigned)l1 << 16);
    }
}

// ---------------------------------------------------------------------------
// QKV GEMM via mma.sync bf16 hi/lo.  cp.async staging, 2 CTAs/SM.
// SMEM: XS fp32[128][64] | AH/AL bf16[128][72] | BH/BL bf16[96][72]
// ---------------------------------------------------------------------------
#define ASTRIDE 72
#define SM_XS 0
#define SM_AH 32768
#define SM_AL 51200
#define SM_BH 69632
#define SM_BL 83456
#define QKV_SMEM 97280

__global__ void __launch_bounds__(256, 2)
qkv_mma_kernel(const float* __restrict__ X, int N)
{
    extern __shared__ char smem[];
    const unsigned sb = smem_u32(smem);
    const int tid  = threadIdx.x;
    const int wid  = tid >> 5;
    const int lane = tid & 31;
    const int n0   = blockIdx.x * 128;

    float acc[12][4];
    #pragma unroll
    for (int j = 0; j < 12; j++)
        #pragma unroll
        for (int i = 0; i < 4; i++) acc[j][i] = 0.f;

    const int a_row = (lane & 15);
    const int a_kh  = ((lane >> 4) & 1) * 8;
    const int b_row = (lane & 7);
    const int b_kh  = ((lane >> 3) & 1) * 8;

    // Issue X chunk 0 -> XS
    #pragma unroll
    for (int ii = 0; ii < 8; ii++) {
        int q = tid + 256 * ii;
        int r = q >> 4, j4 = q & 15;
        int node = n0 + r;
        const float* src = &X[(size_t)(node < N ? node : 0) * IN_DIM + 4 * j4];
        cp16(sb + SM_XS + r * 256 + j4 * 16, src, (node < N) ? 16 : 0);
    }
    CP_COMMIT();

    for (int c = 0; c < 4; c++) {
        CP_WAIT0();            // XS(c) arrived
        __syncthreads();       // ...and prev MMA done reading A/B

        // Issue B chunk c -> BH/BL (contiguous 16B copies)
        for (int i = tid; i < 1728; i += 256) {
            if (i < 864)
                cp16(sb + SM_BH + 16 * i,
                     (const char*)g_Bhp + c * 13824 + 16 * i, 16);
            else
                cp16(sb + SM_BL + 16 * (i - 864),
                     (const char*)g_Blp + c * 13824 + 16 * (i - 864), 16);
        }
        CP_COMMIT();

        // Convert XS -> AH/AL (overlaps B copy in flight)
        #pragma unroll
        for (int ii = 0; ii < 8; ii++) {
            int q = tid + 256 * ii;
            int r = q >> 4, j4 = q & 15;
            float4 v = *(const float4*)(smem + SM_XS + r * 256 + j4 * 16);
            unsigned short hx = bf16h(v.x), hy = bf16h(v.y),
                           hz = bf16h(v.z), hw = bf16h(v.w);
            unsigned short lx = bf16h(v.x - bf16f(hx)), ly = bf16h(v.y - bf16f(hy)),
                           lz = bf16h(v.z - bf16f(hz)), lw = bf16h(v.w - bf16f(hw));
            unsigned byte = r * (ASTRIDE * 2) + 8 * j4;
            *(uint2*)(smem + SM_AH + byte) =
                make_uint2((unsigned)hx | ((unsigned)hy << 16),
                           (unsigned)hz | ((unsigned)hw << 16));
            *(uint2*)(smem + SM_AL + byte) =
                make_uint2((unsigned)lx | ((unsigned)ly << 16),
                           (unsigned)lz | ((unsigned)lw << 16));
        }

        CP_WAIT0();            // B(c) arrived
        __syncthreads();       // conversions visible; XS free for reuse

        // Issue X chunk c+1 (overlaps the MMA block below)
        if (c < 3) {
            #pragma unroll
            for (int ii = 0; ii < 8; ii++) {
                int q = tid + 256 * ii;
                int r = q >> 4, j4 = q & 15;
                int node = n0 + r;
                const float* src =
                    &X[(size_t)(node < N ? node : 0) * IN_DIM + (c + 1) * 64 + 4 * j4];
                cp16(sb + SM_XS + r * 256 + j4 * 16, src, (node < N) ? 16 : 0);
            }
            CP_COMMIT();
        }

        #pragma unroll
        for (int ks = 0; ks < 4; ks++) {
            unsigned ah[4], al[4];
            {
                unsigned byte = (wid * 16 + a_row) * (ASTRIDE * 2)
                              + (ks * 16 + a_kh) * 2;
                ldsm_x4(ah, sb + SM_AH + byte);
                ldsm_x4(al, sb + SM_AL + byte);
            }
            #pragma unroll
            for (int j = 0; j < 12; j++) {
                unsigned bh[2], bl[2];
                unsigned byte = (j * 8 + b_row) * (ASTRIDE * 2)
                              + (ks * 16 + b_kh) * 2;
                ldsm_x2(bh, sb + SM_BH + byte);
                ldsm_x2(bl, sb + SM_BL + byte);
                mma_bf16(acc[j], ah, bh);
                mma_bf16(acc[j], ah, bl);
                mma_bf16(acc[j], al, bh);
            }
        }
    }

    // Epilogue: Q separate; K/V interleaved per node (64-float row)
    const int g  = lane >> 2;
    const int tt = lane & 3;
    const int row_hi = n0 + wid * 16 + g;
    const int row_lo = row_hi + 8;
    #pragma unroll
    for (int j = 0; j < 12; j++) {
        int col = 8 * (j & 3) + 2 * tt;
        float* p_hi;
        float* p_lo;
        if (j < 4) {
            p_hi = &g_Q[(size_t)row_hi * HD + col];
            p_lo = &g_Q[(size_t)row_lo * HD + col];
        } else if (j < 8) {
            p_hi = &g_KV[(size_t)row_hi * 64 + col];
            p_lo = &g_KV[(size_t)row_lo * 64 + col];
        } else {
            p_hi = &g_KV[(size_t)row_hi * 64 + 32 + col];
            p_lo = &g_KV[(size_t)row_lo * 64 + 32 + col];
        }
        if (row_hi < N) *(float2*)p_hi = make_float2(acc[j][0], acc[j][1]);
        if (row_lo < N) *(float2*)p_lo = make_float2(acc[j][2], acc[j][3]);
    }
}

// ---------------------------------------------------------------------------
// CSR hist + scan in ONE kernel (grid-barrier; state self-resets).
// ---------------------------------------------------------------------------
__global__ void __launch_bounds__(SCAN_BLK)
csr_kernel(const int* __restrict__ ei, int E, int N, int nb)
{
    __shared__ int wsum[32];
    __shared__ int sh2[128];
    __shared__ int s_boff;

    const int t    = threadIdx.x;
    const int lane = t & 31;
    const int wid  = t >> 5;
    const int b    = blockIdx.x;
    const int gtid = b * SCAN_BLK + t;
    const int gsz  = nb * SCAN_BLK;

    const int nquad = E >> 2;
    for (int q = gtid; q < nquad; q += gsz) {
        int4 s = ((const int4*)ei)[q];
        atomicAdd(&g_cnt[s.x], 1);
        atomicAdd(&g_cnt[s.y], 1);
        atomicAdd(&g_cnt[s.z], 1);
        atomicAdd(&g_cnt[s.w], 1);
    }
    for (int e = (nquad << 2) + gtid; e < E; e += gsz)
        atomicAdd(&g_cnt[ei[e]], 1);

    __syncthreads();
    if (t == 0) {
        __threadfence();
        int ticket = atomicAdd(&g_bar1, 1);
        if (ticket == nb - 1) atomicExch(&g_rel1, 1);
        while (atomicAdd(&g_rel1, 0) == 0) {}
        __threadfence();
    }
    __syncthreads();

    const int i = gtid;
    int v = (i < N) ? g_cnt[i] : 0;
    int x = v;
    #pragma unroll
    for (int off = 1; off < 32; off <<= 1) {
        int y = __shfl_up_sync(0xffffffffu, x, off);
        if (lane >= off) x += y;
    }
    if (lane == 31) wsum[wid] = x;
    __syncthreads();
    if (wid == 0) {
        int s = wsum[lane];
        #pragma unroll
        for (int off = 1; off < 32; off <<= 1) {
            int y = __shfl_up_sync(0xffffffffu, s, off);
            if (lane >= off) s += y;
        }
        wsum[lane] = s;
    }
    __syncthreads();
    const int base = (wid > 0) ? wsum[wid - 1] : 0;
    const int excl = base + x - v;

    if (t == SCAN_BLK - 1) {
        g_bsum[b] = base + x;
        __threadfence();
        atomicExch(&g_ready[b], 1);
    }

    int val = 0;
    if (t < nb) {
        while (atomicAdd(&g_ready[t], 0) == 0) {}
        __threadfence();
        val = g_bsum[t];
    }
    if (t < 128) sh2[t] = (t < nb) ? val : 0;
    __syncthreads();
    #pragma unroll
    for (int off = 1; off < 128; off <<= 1) {
        int y = (t < 128 && t >= off) ? sh2[t - off] : 0;
        __syncthreads();
        if (t < 128) sh2[t] += y;
        __syncthreads();
    }
    if (t == b) s_boff = sh2[b] - val;
    __syncthreads();

    if (i < N) {
        int rp = s_boff + excl;
        g_rowptr[i] = rp;
        g_cursor[i] = rp;
    }

    __syncthreads();
    if (t == 0) {
        int d = atomicAdd(&g_done1, 1);
        if (d == nb - 1) {
            for (int k = 0; k < nb; k++) g_ready[k] = 0;
            g_bar1 = 0;
            g_rel1 = 0;
            g_done1 = 0;
            __threadfence();
        }
    }
}

__global__ void scatter_kernel(const int* __restrict__ ei, int E)
{
    int b = (blockIdx.x * blockDim.x + threadIdx.x) * 4;
    if (b + 3 < E) {
        int4 s = *(const int4*)&ei[b];
        int4 d = *(const int4*)&ei[E + b];
        g_sdst[atomicAdd(&g_cursor[s.x], 1)] = d.x;
        g_sdst[atomicAdd(&g_cursor[s.y], 1)] = d.y;
        g_sdst[atomicAdd(&g_cursor[s.z], 1)] = d.z;
        g_sdst[atomicAdd(&g_cursor[s.w], 1)] = d.w;
    } else {
        for (int e = b; e < E; e++) {
            int s = ei[e];
            int d = ei[E + e];
            g_sdst[atomicAdd(&g_cursor[s], 1)] = d;
        }
    }
}

// ---------------------------------------------------------------------------
// Fused softmax + aggregate (R12, measured 36.6us): FOUR nodes per warp,
// one 8-lane group per node, 2-edge unroll with index prefetch.
// ---------------------------------------------------------------------------
__global__ void __launch_bounds__(256)
agg_kernel(float* __restrict__ out, int N)
{
    const int lane = threadIdx.x & 31;
    const int warp = (blockIdx.x * blockDim.x + threadIdx.x) >> 5;
    const int grp  = lane >> 3;
    const int sub  = lane & 7;
    const int n    = warp * 4 + grp;
    const bool nvalid = (n < N);
    const int nn   = nvalid ? n : 0;

    const float4 q4 = *(const float4*)&g_Q[(size_t)nn * HD + sub * 4];
    const int rs  = g_rowptr[nn];
    const int cnt = nvalid ? g_cnt[nn] : 0;

    int nit = (cnt + 1) >> 1;
    nit = max(nit, __shfl_xor_sync(0xffffffffu, nit, 8));
    nit = max(nit, __shfl_xor_sync(0xffffffffu, nit, 16));

    float4 acc = make_float4(0.f, 0.f, 0.f, 0.f);
    float  sw  = 0.f;

    bool v0 = (0 < cnt);
    bool v1 = (1 < cnt);
    int  d0 = v0 ? g_sdst[rs] : 0;
    int  d1 = v1 ? g_sdst[rs + 1] : 0;

    for (int it = 0; it < nit; it++) {
        float4 k0 = make_float4(0.f, 0.f, 0.f, 0.f), u0 = k0, k1 = k0, u1 = k0;
        if (v0) {
            const float* kv = &g_KV[(size_t)d0 * 64];
            k0 = *(const float4*)&kv[sub * 4];
            u0 = *(const float4*)&kv[32 + sub * 4];
        }
        if (v1) {
            const float* kv = &g_KV[(size_t)d1 * 64];
            k1 = *(const float4*)&kv[sub * 4];
            u1 = *(const float4*)&kv[32 + sub * 4];
        }

        bool nv0 = false, nv1 = false;
        int  nd0 = 0, nd1 = 0;
        {
            int e = (it + 1) * 2;
            nv0 = (e < cnt);
            nv1 = (e + 1 < cnt);
            nd0 = nv0 ? g_sdst[rs + e] : 0;
            nd1 = nv1 ? g_sdst[rs + e + 1] : 0;
        }

        float p0 = q4.x * k0.x + q4.y * k0.y + q4.z * k0.z + q4.w * k0.w;
        float p1 = q4.x * k1.x + q4.y * k1.y + q4.z * k1.z + q4.w * k1.w;
        p0 += __shfl_xor_sync(0xffffffffu, p0, 1);
        p1 += __shfl_xor_sync(0xffffffffu, p1, 1);
        p0 += __shfl_xor_sync(0xffffffffu, p0, 2);
        p1 += __shfl_xor_sync(0xffffffffu, p1, 2);
        p0 += __shfl_xor_sync(0xffffffffu, p0, 4);
        p1 += __shfl_xor_sync(0xffffffffu, p1, 4);

        float w0 = v0 ? __expf(p0 * 0.17677669529663687f) : 0.f;
        float w1 = v1 ? __expf(p1 * 0.17677669529663687f) : 0.f;
        sw += w0 + w1;

        acc.x += w0 * u0.x + w1 * u1.x;
        acc.y += w0 * u0.y + w1 * u1.y;
        acc.z += w0 * u0.z + w1 * u1.z;
        acc.w += w0 * u0.w + w1 * u1.w;

        v0 = nv0; v1 = nv1; d0 = nd0; d1 = nd1;
    }

    if (nvalid) {
        if (sub == 0) g_cnt[n] = 0;
        float inv = (sw > 0.f) ? (1.f / sw) : 0.f;
        float4 o = make_float4(acc.x * inv, acc.y * inv, acc.z * inv, acc.w * inv);
        *(float4*)&out[(size_t)n * HD + sub * 4] = o;
    }
}

// ---------------------------------------------------------------------------
// Launch: 5 kernels, fork-join across two streams.
//   csr(1,s0)  scatter(2,s0)  bprep(3,s1)  qkv(4,s1 <- profiled)  agg(5,s0)
// ---------------------------------------------------------------------------
extern "C" void kernel_launch(void* const* d_in, const int* in_sizes, int n_in,
                              void* d_out, int out_size)
{
    const float* X  = (const float*)d_in[0];
    const int*   ei = (const int*)d_in[1];     // int32 edge indices
    const float* Wq = (const float*)d_in[2];
    const float* Wk = (const float*)d_in[3];
    const float* Wv = (const float*)d_in[4];
    float* out = (float*)d_out;

    const int N = in_sizes[0] / IN_DIM;
    const int E = in_sizes[1] / 2;
    const int nb = (N + SCAN_BLK - 1) / SCAN_BLK;

    static cudaStream_t s1 = nullptr;
    static cudaEvent_t  evF = nullptr, evA = nullptr;
    if (!s1) {
        cudaFuncSetAttribute(qkv_mma_kernel,
                             cudaFuncAttributeMaxDynamicSharedMemorySize,
                             QKV_SMEM);
        cudaStreamCreateWithFlags(&s1, cudaStreamNonBlocking);
        cudaEventCreateWithFlags(&evF, cudaEventDisableTiming);
        cudaEventCreateWithFlags(&evA, cudaEventDisableTiming);
    }

    // Fork
    cudaEventRecord(evF, 0);
    cudaStreamWaitEvent(s1, evF, 0);

    csr_kernel<<<nb, SCAN_BLK>>>(ei, E, N, nb);                        // 1
    scatter_kernel<<<(E / 4 + 255) / 256, 256>>>(ei, E);               // 2
    bprep_kernel<<<1, 256, 0, s1>>>(Wq, Wk, Wv);                       // 3
    qkv_mma_kernel<<<(N + 127) / 128, 256, QKV_SMEM, s1>>>(X, N);      // 4 <- profiled
    cudaEventRecord(evA, s1);

    // Join
    cudaStreamWaitEvent(0, evA, 0);
    agg_kernel<<<((N * 8) + 255) / 256, 256>>>(out, N);                // 5
}

// round 15
// speedup vs baseline: 1.2428x; 1.1055x over previous
#include <cuda_runtime.h>
#include <cuda_bf16.h>

// ---------------------------------------------------------------------------
// GAT-style sparse attention, CSR-fused formulation.  5 launches:
//   csr(1,s0)  scatter(2,s0)  bprep(3,s1)  qkv(4,s1 <- profiled)  agg(5,s0)
// qkv: mma.sync bf16 hi/lo, cp.async staging, BM=64, 3 CTAs/SM (24 warps).
// agg: 4 nodes/warp, 8-lane group per node, 2-edge unroll (R12, measured).
// edge_index arrives as int32.  Plain sm_103 target: mma.sync/ldmatrix/cp.async.
// ---------------------------------------------------------------------------

#define IN_DIM 256
#define HD 32
#define NMAX 100000
#define EMAX 1600000
#define SCAN_BLK 1024

__device__ __align__(16) float g_Q[NMAX * HD];
__device__ __align__(16) float g_KV[NMAX * 64];   // per node: K[0:32) | V[32:64)
__device__ int g_cnt[NMAX];       // zero at load; agg re-zeros for next call
__device__ int g_rowptr[NMAX];
__device__ int g_cursor[NMAX];
__device__ __align__(16) int g_sdst[EMAX];
__device__ int g_bsum[128];
// csr_kernel sync state (all zero at load; self-resetting each run)
__device__ int g_bar1, g_rel1, g_done1;
__device__ int g_ready[128];
// Pre-built bf16 hi/lo of B=W^T in padded smem layout:
// [4 chunks][96 rows][36 uints] (144B rows; last 16B padding, never read)
__device__ __align__(16) unsigned g_Bhp[4 * 96 * 36];
__device__ __align__(16) unsigned g_Blp[4 * 96 * 36];

// ---------------------------------------------------------------------------
// helpers
// ---------------------------------------------------------------------------
__device__ __forceinline__ unsigned smem_u32(const void* p)
{
    unsigned a;
    asm("{ .reg .u64 t; cvta.to.shared.u64 t, %1; cvt.u32.u64 %0, t; }"
        : "=r"(a) : "l"(p));
    return a;
}
__device__ __forceinline__ unsigned short bf16h(float x)
{
    return __bfloat16_as_ushort(__float2bfloat16(x));
}
__device__ __forceinline__ float bf16f(unsigned short u)
{
    return __bfloat162float(__ushort_as_bfloat16(u));
}

__device__ __forceinline__ void cp16(unsigned dst, const void* src, int srcsz)
{
    asm volatile("cp.async.cg.shared.global [%0], [%1], 16, %2;"
                 :: "r"(dst),
                    "l"(__cvta_generic_to_global(src)),
                    "r"(srcsz) : "memory");
}
#define CP_COMMIT() asm volatile("cp.async.commit_group;" ::: "memory")
#define CP_WAIT0()  asm volatile("cp.async.wait_group 0;" ::: "memory")

__device__ __forceinline__ void ldsm_x4(unsigned r[4], unsigned addr)
{
    asm volatile("ldmatrix.sync.aligned.m8n8.x4.shared.b16 {%0,%1,%2,%3}, [%4];"
                 : "=r"(r[0]), "=r"(r[1]), "=r"(r[2]), "=r"(r[3]) : "r"(addr));
}
__device__ __forceinline__ void ldsm_x2(unsigned r[2], unsigned addr)
{
    asm volatile("ldmatrix.sync.aligned.m8n8.x2.shared.b16 {%0,%1}, [%2];"
                 : "=r"(r[0]), "=r"(r[1]) : "r"(addr));
}
__device__ __forceinline__ void mma_bf16(float c[4], const unsigned a[4],
                                         const unsigned b[2])
{
    asm volatile("mma.sync.aligned.m16n8k16.row.col.f32.bf16.bf16.f32 "
                 "{%0,%1,%2,%3}, {%4,%5,%6,%7}, {%8,%9}, {%0,%1,%2,%3};"
                 : "+f"(c[0]), "+f"(c[1]), "+f"(c[2]), "+f"(c[3])
                 : "r"(a[0]), "r"(a[1]), "r"(a[2]), "r"(a[3]),
                   "r"(b[0]), "r"(b[1]));
}

// ---------------------------------------------------------------------------
// B prep: bf16 hi/lo of W^T in PADDED layout (144B rows).  48 blocks.
// ---------------------------------------------------------------------------
__global__ void bprep_kernel(const float* __restrict__ Wq,
                             const float* __restrict__ Wk,
                             const float* __restrict__ Wv)
{
    int idx = blockIdx.x * blockDim.x + threadIdx.x;   // 0..12287
    if (idx >= 12288) return;
    int c   = idx / 3072;
    int rem = idx % 3072;
    int n   = rem / 32;
    int jp  = rem % 32;
    int k0  = c * 64 + 2 * jp;
    const float* Wm = (n < 32) ? Wq : (n < 64) ? Wk : Wv;
    float w0 = Wm[k0 * HD + (n & 31)];
    float w1 = Wm[(k0 + 1) * HD + (n & 31)];
    unsigned short h0 = bf16h(w0), h1 = bf16h(w1);
    unsigned short l0 = bf16h(w0 - bf16f(h0));
    unsigned short l1 = bf16h(w1 - bf16f(h1));
    int g = c * 3456 + n * 36 + jp;
    g_Bhp[g] = (unsigned)h0 | ((unsigned)h1 << 16);
    g_Blp[g] = (unsigned)l0 | ((unsigned)l1 << 16);
}

// ---------------------------------------------------------------------------
// QKV GEMM via mma.sync bf16 hi/lo.  BM=64 rows/CTA, 256 thr (8 warps =
// 4 M-slabs x 2 N-halves), cp.async staging, 3 CTAs/SM.
// SMEM: XS fp32[64][64] | AH/AL bf16[64][72] | BH/BL bf16[96][72]
// ---------------------------------------------------------------------------
#define ASTRIDE 72
#define SM_XS 0
#define SM_AH 16384
#define SM_AL 25600
#define SM_BH 34816
#define SM_BL 48640
#define QKV_SMEM 62464

__global__ void __launch_bounds__(256, 3)
qkv_mma_kernel(const float* __restrict__ X, int N)
{
    extern __shared__ char smem[];
    const unsigned sb = smem_u32(smem);
    const int tid   = threadIdx.x;
    const int wid   = tid >> 5;
    const int lane  = tid & 31;
    const int mslab = wid & 3;        // 16-row slab 0..3
    const int nhalf = wid >> 2;       // cols [nhalf*48, +48)
    const int n0    = blockIdx.x * 64;

    float acc[6][4];
    #pragma unroll
    for (int j = 0; j < 6; j++)
        #pragma unroll
        for (int i = 0; i < 4; i++) acc[j][i] = 0.f;

    const int a_row = (lane & 15);
    const int a_kh  = ((lane >> 4) & 1) * 8;
    const int b_row = (lane & 7);
    const int b_kh  = ((lane >> 3) & 1) * 8;

    // Issue X chunk 0 -> XS   (64 rows x 16 float4 = 1024 tasks, 4/thread)
    #pragma unroll
    for (int ii = 0; ii < 4; ii++) {
        int q = tid + 256 * ii;
        int r = q >> 4, j4 = q & 15;
        int node = n0 + r;
        const float* src = &X[(size_t)(node < N ? node : 0) * IN_DIM + 4 * j4];
        cp16(sb + SM_XS + r * 256 + j4 * 16, src, (node < N) ? 16 : 0);
    }
    CP_COMMIT();

    for (int c = 0; c < 4; c++) {
        CP_WAIT0();            // XS(c) arrived
        __syncthreads();       // ...and prev MMA done reading A/B

        // Issue B chunk c -> BH/BL
        for (int i = tid; i < 1728; i += 256) {
            if (i < 864)
                cp16(sb + SM_BH + 16 * i,
                     (const char*)g_Bhp + c * 13824 + 16 * i, 16);
            else
                cp16(sb + SM_BL + 16 * (i - 864),
                     (const char*)g_Blp + c * 13824 + 16 * (i - 864), 16);
        }
        CP_COMMIT();

        // Convert XS -> AH/AL (overlaps B copy in flight)
        #pragma unroll
        for (int ii = 0; ii < 4; ii++) {
            int q = tid + 256 * ii;
            int r = q >> 4, j4 = q & 15;
            float4 v = *(const float4*)(smem + SM_XS + r * 256 + j4 * 16);
            unsigned short hx = bf16h(v.x), hy = bf16h(v.y),
                           hz = bf16h(v.z), hw = bf16h(v.w);
            unsigned short lx = bf16h(v.x - bf16f(hx)), ly = bf16h(v.y - bf16f(hy)),
                           lz = bf16h(v.z - bf16f(hz)), lw = bf16h(v.w - bf16f(hw));
            unsigned byte = r * (ASTRIDE * 2) + 8 * j4;
            *(uint2*)(smem + SM_AH + byte) =
                make_uint2((unsigned)hx | ((unsigned)hy << 16),
                           (unsigned)hz | ((unsigned)hw << 16));
            *(uint2*)(smem + SM_AL + byte) =
                make_uint2((unsigned)lx | ((unsigned)ly << 16),
                           (unsigned)lz | ((unsigned)lw << 16));
        }

        CP_WAIT0();            // B(c) arrived
        __syncthreads();       // conversions visible; XS free for reuse

        // Issue X chunk c+1 (overlaps the MMA block below)
        if (c < 3) {
            #pragma unroll
            for (int ii = 0; ii < 4; ii++) {
                int q = tid + 256 * ii;
                int r = q >> 4, j4 = q & 15;
                int node = n0 + r;
                const float* src =
                    &X[(size_t)(node < N ? node : 0) * IN_DIM + (c + 1) * 64 + 4 * j4];
                cp16(sb + SM_XS + r * 256 + j4 * 16, src, (node < N) ? 16 : 0);
            }
            CP_COMMIT();
        }

        #pragma unroll
        for (int ks = 0; ks < 4; ks++) {
            unsigned ah[4], al[4];
            {
                unsigned byte = (mslab * 16 + a_row) * (ASTRIDE * 2)
                              + (ks * 16 + a_kh) * 2;
                ldsm_x4(ah, sb + SM_AH + byte);
                ldsm_x4(al, sb + SM_AL + byte);
            }
            #pragma unroll
            for (int j = 0; j < 6; j++) {
                int jj = nhalf * 6 + j;
                unsigned bh[2], bl[2];
                unsigned byte = (jj * 8 + b_row) * (ASTRIDE * 2)
                              + (ks * 16 + b_kh) * 2;
                ldsm_x2(bh, sb + SM_BH + byte);
                ldsm_x2(bl, sb + SM_BL + byte);
                mma_bf16(acc[j], ah, bh);
                mma_bf16(acc[j], ah, bl);
                mma_bf16(acc[j], al, bh);
            }
        }
    }

    // Epilogue: Q separate; K/V interleaved per node (64-float row)
    const int g  = lane >> 2;
    const int tt = lane & 3;
    const int row_hi = n0 + mslab * 16 + g;
    const int row_lo = row_hi + 8;
    #pragma unroll
    for (int j = 0; j < 6; j++) {
        int jj  = nhalf * 6 + j;
        int col = 8 * (jj & 3) + 2 * tt;
        float* p_hi;
        float* p_lo;
        if (jj < 4) {
            p_hi = &g_Q[(size_t)row_hi * HD + col];
            p_lo = &g_Q[(size_t)row_lo * HD + col];
        } else if (jj < 8) {
            p_hi = &g_KV[(size_t)row_hi * 64 + col];
            p_lo = &g_KV[(size_t)row_lo * 64 + col];
        } else {
            p_hi = &g_KV[(size_t)row_hi * 64 + 32 + col];
            p_lo = &g_KV[(size_t)row_lo * 64 + 32 + col];
        }
        if (row_hi < N) *(float2*)p_hi = make_float2(acc[j][0], acc[j][1]);
        if (row_lo < N) *(float2*)p_lo = make_float2(acc[j][2], acc[j][3]);
    }
}

// ---------------------------------------------------------------------------
// CSR hist + scan in ONE kernel (grid-barrier; state self-resets).
// ---------------------------------------------------------------------------
__global__ void __launch_bounds__(SCAN_BLK)
csr_kernel(const int* __restrict__ ei, int E, int N, int nb)
{
    __shared__ int wsum[32];
    __shared__ int sh2[128];
    __shared__ int s_boff;

    const int t    = threadIdx.x;
    const int lane = t & 31;
    const int wid  = t >> 5;
    const int b    = blockIdx.x;
    const int gtid = b * SCAN_BLK + t;
    const int gsz  = nb * SCAN_BLK;

    const int nquad = E >> 2;
    for (int q = gtid; q < nquad; q += gsz) {
        int4 s = ((const int4*)ei)[q];
        atomicAdd(&g_cnt[s.x], 1);
        atomicAdd(&g_cnt[s.y], 1);
        atomicAdd(&g_cnt[s.z], 1);
        atomicAdd(&g_cnt[s.w], 1);
    }
    for (int e = (nquad << 2) + gtid; e < E; e += gsz)
        atomicAdd(&g_cnt[ei[e]], 1);

    __syncthreads();
    if (t == 0) {
        __threadfence();
        int ticket = atomicAdd(&g_bar1, 1);
        if (ticket == nb - 1) atomicExch(&g_rel1, 1);
        while (atomicAdd(&g_rel1, 0) == 0) {}
        __threadfence();
    }
    __syncthreads();

    const int i = gtid;
    int v = (i < N) ? g_cnt[i] : 0;
    int x = v;
    #pragma unroll
    for (int off = 1; off < 32; off <<= 1) {
        int y = __shfl_up_sync(0xffffffffu, x, off);
        if (lane >= off) x += y;
    }
    if (lane == 31) wsum[wid] = x;
    __syncthreads();
    if (wid == 0) {
        int s = wsum[lane];
        #pragma unroll
        for (int off = 1; off < 32; off <<= 1) {
            int y = __shfl_up_sync(0xffffffffu, s, off);
            if (lane >= off) s += y;
        }
        wsum[lane] = s;
    }
    __syncthreads();
    const int base = (wid > 0) ? wsum[wid - 1] : 0;
    const int excl = base + x - v;

    if (t == SCAN_BLK - 1) {
        g_bsum[b] = base + x;
        __threadfence();
        atomicExch(&g_ready[b], 1);
    }

    int val = 0;
    if (t < nb) {
        while (atomicAdd(&g_ready[t], 0) == 0) {}
        __threadfence();
        val = g_bsum[t];
    }
    if (t < 128) sh2[t] = (t < nb) ? val : 0;
    __syncthreads();
    #pragma unroll
    for (int off = 1; off < 128; off <<= 1) {
        int y = (t < 128 && t >= off) ? sh2[t - off] : 0;
        __syncthreads();
        if (t < 128) sh2[t] += y;
        __syncthreads();
    }
    if (t == b) s_boff = sh2[b] - val;
    __syncthreads();

    if (i < N) {
        int rp = s_boff + excl;
        g_rowptr[i] = rp;
        g_cursor[i] = rp;
    }

    __syncthreads();
    if (t == 0) {
        int d = atomicAdd(&g_done1, 1);
        if (d == nb - 1) {
            for (int k = 0; k < nb; k++) g_ready[k] = 0;
            g_bar1 = 0;
            g_rel1 = 0;
            g_done1 = 0;
            __threadfence();
        }
    }
}

__global__ void scatter_kernel(const int* __restrict__ ei, int E)
{
    int b = (blockIdx.x * blockDim.x + threadIdx.x) * 4;
    if (b + 3 < E) {
        int4 s = *(const int4*)&ei[b];
        int4 d = *(const int4*)&ei[E + b];
        g_sdst[atomicAdd(&g_cursor[s.x], 1)] = d.x;
        g_sdst[atomicAdd(&g_cursor[s.y], 1)] = d.y;
        g_sdst[atomicAdd(&g_cursor[s.z], 1)] = d.z;
        g_sdst[atomicAdd(&g_cursor[s.w], 1)] = d.w;
    } else {
        for (int e = b; e < E; e++) {
            int s = ei[e];
            int d = ei[E + e];
            g_sdst[atomicAdd(&g_cursor[s], 1)] = d;
        }
    }
}

// ---------------------------------------------------------------------------
// Fused softmax + aggregate (R12, measured 36.6us): FOUR nodes per warp,
// one 8-lane group per node, 2-edge unroll with index prefetch.
// ---------------------------------------------------------------------------
__global__ void __launch_bounds__(256)
agg_kernel(float* __restrict__ out, int N)
{
    const int lane = threadIdx.x & 31;
    const int warp = (blockIdx.x * blockDim.x + threadIdx.x) >> 5;
    const int grp  = lane >> 3;
    const int sub  = lane & 7;
    const int n    = warp * 4 + grp;
    const bool nvalid = (n < N);
    const int nn   = nvalid ? n : 0;

    const float4 q4 = *(const float4*)&g_Q[(size_t)nn * HD + sub * 4];
    const int rs  = g_rowptr[nn];
    const int cnt = nvalid ? g_cnt[nn] : 0;

    int nit = (cnt + 1) >> 1;
    nit = max(nit, __shfl_xor_sync(0xffffffffu, nit, 8));
    nit = max(nit, __shfl_xor_sync(0xffffffffu, nit, 16));

    float4 acc = make_float4(0.f, 0.f, 0.f, 0.f);
    float  sw  = 0.f;

    bool v0 = (0 < cnt);
    bool v1 = (1 < cnt);
    int  d0 = v0 ? g_sdst[rs] : 0;
    int  d1 = v1 ? g_sdst[rs + 1] : 0;

    for (int it = 0; it < nit; it++) {
        float4 k0 = make_float4(0.f, 0.f, 0.f, 0.f), u0 = k0, k1 = k0, u1 = k0;
        if (v0) {
            const float* kv = &g_KV[(size_t)d0 * 64];
            k0 = *(const float4*)&kv[sub * 4];
            u0 = *(const float4*)&kv[32 + sub * 4];
        }
        if (v1) {
            const float* kv = &g_KV[(size_t)d1 * 64];
            k1 = *(const float4*)&kv[sub * 4];
            u1 = *(const float4*)&kv[32 + sub * 4];
        }

        bool nv0 = false, nv1 = false;
        int  nd0 = 0, nd1 = 0;
        {
            int e = (it + 1) * 2;
            nv0 = (e < cnt);
            nv1 = (e + 1 < cnt);
            nd0 = nv0 ? g_sdst[rs + e] : 0;
            nd1 = nv1 ? g_sdst[rs + e + 1] : 0;
        }

        float p0 = q4.x * k0.x + q4.y * k0.y + q4.z * k0.z + q4.w * k0.w;
        float p1 = q4.x * k1.x + q4.y * k1.y + q4.z * k1.z + q4.w * k1.w;
        p0 += __shfl_xor_sync(0xffffffffu, p0, 1);
        p1 += __shfl_xor_sync(0xffffffffu, p1, 1);
        p0 += __shfl_xor_sync(0xffffffffu, p0, 2);
        p1 += __shfl_xor_sync(0xffffffffu, p1, 2);
        p0 += __shfl_xor_sync(0xffffffffu, p0, 4);
        p1 += __shfl_xor_sync(0xffffffffu, p1, 4);

        float w0 = v0 ? __expf(p0 * 0.17677669529663687f) : 0.f;
        float w1 = v1 ? __expf(p1 * 0.17677669529663687f) : 0.f;
        sw += w0 + w1;

        acc.x += w0 * u0.x + w1 * u1.x;
        acc.y += w0 * u0.y + w1 * u1.y;
        acc.z += w0 * u0.z + w1 * u1.z;
        acc.w += w0 * u0.w + w1 * u1.w;

        v0 = nv0; v1 = nv1; d0 = nd0; d1 = nd1;
    }

    if (nvalid) {
        if (sub == 0) g_cnt[n] = 0;
        float inv = (sw > 0.f) ? (1.f / sw) : 0.f;
        float4 o = make_float4(acc.x * inv, acc.y * inv, acc.z * inv, acc.w * inv);
        *(float4*)&out[(size_t)n * HD + sub * 4] = o;
    }
}

// ---------------------------------------------------------------------------
// Launch: 5 kernels, fork-join across two streams.
//   csr(1,s0)  scatter(2,s0)  bprep(3,s1)  qkv(4,s1 <- profiled)  agg(5,s0)
// ---------------------------------------------------------------------------
extern "C" void kernel_launch(void* const* d_in, const int* in_sizes, int n_in,
                              void* d_out, int out_size)
{
    const float* X  = (const float*)d_in[0];
    const int*   ei = (const int*)d_in[1];     // int32 edge indices
    const float* Wq = (const float*)d_in[2];
    const float* Wk = (const float*)d_in[3];
    const float* Wv = (const float*)d_in[4];
    float* out = (float*)d_out;

    const int N = in_sizes[0] / IN_DIM;
    const int E = in_sizes[1] / 2;
    const int nb = (N + SCAN_BLK - 1) / SCAN_BLK;

    static cudaStream_t s1 = nullptr;
    static cudaEvent_t  evF = nullptr, evA = nullptr;
    if (!s1) {
        cudaFuncSetAttribute(qkv_mma_kernel,
                             cudaFuncAttributeMaxDynamicSharedMemorySize,
                             QKV_SMEM);
        cudaStreamCreateWithFlags(&s1, cudaStreamNonBlocking);
        cudaEventCreateWithFlags(&evF, cudaEventDisableTiming);
        cudaEventCreateWithFlags(&evA, cudaEventDisableTiming);
    }

    // Fork
    cudaEventRecord(evF, 0);
    cudaStreamWaitEvent(s1, evF, 0);

    csr_kernel<<<nb, SCAN_BLK>>>(ei, E, N, nb);                        // 1
    scatter_kernel<<<(E / 4 + 255) / 256, 256>>>(ei, E);               // 2
    bprep_kernel<<<48, 256, 0, s1>>>(Wq, Wk, Wv);                      // 3
    qkv_mma_kernel<<<(N + 63) / 64, 256, QKV_SMEM, s1>>>(X, N);        // 4 <- profiled
    cudaEventRecord(evA, s1);

    // Join
    cudaStreamWaitEvent(0, evA, 0);
    agg_kernel<<<((N * 8) + 255) / 256, 256>>>(out, N);                // 5
}

// round 16
// speedup vs baseline: 1.3395x; 1.0779x over previous
#include <cuda_runtime.h>
#include <cuda_bf16.h>

// ---------------------------------------------------------------------------
// GAT-style sparse attention, CSR-fused formulation.  5 launches:
//   csr(1,s0)  scatter(2,s0)  bprep(3,s1)  qkv(4,s1 <- profiled)  agg(5,s0)
// qkv: mma.sync bf16 hi/lo.  BM=128, 8 warps = 4 M-pairs(32 rows) x 2 N-halves
//      (B fragments reused across 2 A slabs -> L1 ldsm traffic -40%),
//      X via LDG reg prefetch (no XS staging), B via cp.async, 2 CTAs/SM.
// agg: 4 nodes/warp, 8-lane group per node, 2-edge unroll (R12, measured).
// edge_index arrives as int32.  Plain sm_103 target: mma.sync/ldmatrix/cp.async.
// ---------------------------------------------------------------------------

#define IN_DIM 256
#define HD 32
#define NMAX 100000
#define EMAX 1600000
#define SCAN_BLK 1024

__device__ __align__(16) float g_Q[NMAX * HD];
__device__ __align__(16) float g_KV[NMAX * 64];   // per node: K[0:32) | V[32:64)
__device__ int g_cnt[NMAX];       // zero at load; agg re-zeros for next call
__device__ int g_rowptr[NMAX];
__device__ int g_cursor[NMAX];
__device__ __align__(16) int g_sdst[EMAX];
__device__ int g_bsum[128];
// csr_kernel sync state (all zero at load; self-resetting each run)
__device__ int g_bar1, g_rel1, g_done1;
__device__ int g_ready[128];
// Pre-built bf16 hi/lo of B=W^T in padded smem layout:
// [4 chunks][96 rows][36 uints] (144B rows; last 16B padding, never read)
__device__ __align__(16) unsigned g_Bhp[4 * 96 * 36];
__device__ __align__(16) unsigned g_Blp[4 * 96 * 36];

// ---------------------------------------------------------------------------
// helpers
// ---------------------------------------------------------------------------
__device__ __forceinline__ unsigned smem_u32(const void* p)
{
    unsigned a;
    asm("{ .reg .u64 t; cvta.to.shared.u64 t, %1; cvt.u32.u64 %0, t; }"
        : "=r"(a) : "l"(p));
    return a;
}
__device__ __forceinline__ unsigned short bf16h(float x)
{
    return __bfloat16_as_ushort(__float2bfloat16(x));
}
__device__ __forceinline__ float bf16f(unsigned short u)
{
    return __bfloat162float(__ushort_as_bfloat16(u));
}

__device__ __forceinline__ void cp16(unsigned dst, const void* src, int srcsz)
{
    asm volatile("cp.async.cg.shared.global [%0], [%1], 16, %2;"
                 :: "r"(dst),
                    "l"(__cvta_generic_to_global(src)),
                    "r"(srcsz) : "memory");
}
#define CP_COMMIT() asm volatile("cp.async.commit_group;" ::: "memory")
#define CP_WAIT0()  asm volatile("cp.async.wait_group 0;" ::: "memory")

__device__ __forceinline__ void ldsm_x4(unsigned r[4], unsigned addr)
{
    asm volatile("ldmatrix.sync.aligned.m8n8.x4.shared.b16 {%0,%1,%2,%3}, [%4];"
                 : "=r"(r[0]), "=r"(r[1]), "=r"(r[2]), "=r"(r[3]) : "r"(addr));
}
__device__ __forceinline__ void ldsm_x2(unsigned r[2], unsigned addr)
{
    asm volatile("ldmatrix.sync.aligned.m8n8.x2.shared.b16 {%0,%1}, [%2];"
                 : "=r"(r[0]), "=r"(r[1]) : "r"(addr));
}
__device__ __forceinline__ void mma_bf16(float c[4], const unsigned a[4],
                                         const unsigned b[2])
{
    asm volatile("mma.sync.aligned.m16n8k16.row.col.f32.bf16.bf16.f32 "
                 "{%0,%1,%2,%3}, {%4,%5,%6,%7}, {%8,%9}, {%0,%1,%2,%3};"
                 : "+f"(c[0]), "+f"(c[1]), "+f"(c[2]), "+f"(c[3])
                 : "r"(a[0]), "r"(a[1]), "r"(a[2]), "r"(a[3]),
                   "r"(b[0]), "r"(b[1]));
}

// ---------------------------------------------------------------------------
// B prep: bf16 hi/lo of W^T in PADDED layout (144B rows).  48 blocks.
// ---------------------------------------------------------------------------
__global__ void bprep_kernel(const float* __restrict__ Wq,
                             const float* __restrict__ Wk,
                             const float* __restrict__ Wv)
{
    int idx = blockIdx.x * blockDim.x + threadIdx.x;   // 0..12287
    if (idx >= 12288) return;
    int c   = idx / 3072;
    int rem = idx % 3072;
    int n   = rem / 32;
    int jp  = rem % 32;
    int k0  = c * 64 + 2 * jp;
    const float* Wm = (n < 32) ? Wq : (n < 64) ? Wk : Wv;
    float w0 = Wm[k0 * HD + (n & 31)];
    float w1 = Wm[(k0 + 1) * HD + (n & 31)];
    unsigned short h0 = bf16h(w0), h1 = bf16h(w1);
    unsigned short l0 = bf16h(w0 - bf16f(h0));
    unsigned short l1 = bf16h(w1 - bf16f(h1));
    int g = c * 3456 + n * 36 + jp;
    g_Bhp[g] = (unsigned)h0 | ((unsigned)h1 << 16);
    g_Blp[g] = (unsigned)l0 | ((unsigned)l1 << 16);
}

// ---------------------------------------------------------------------------
// QKV GEMM via mma.sync bf16 hi/lo.  BM=128, 256 thr, 8 warps =
// 4 M-pairs (32 rows: 2 slabs) x 2 N-halves (6 tiles).  2 CTAs/SM.
// SMEM: AH/AL bf16[128][72] | BH/BL bf16[96][72]  (no XS staging)
// ---------------------------------------------------------------------------
#define ASTRIDE 72
#define SM_AH 0
#define SM_AL 18432
#define SM_BH 36864
#define SM_BL 50688
#define QKV_SMEM 64512

__global__ void __launch_bounds__(256, 2)
qkv_mma_kernel(const float* __restrict__ X, int N)
{
    extern __shared__ char smem[];
    const unsigned sb = smem_u32(smem);
    const int tid   = threadIdx.x;
    const int wid   = tid >> 5;
    const int lane  = tid & 31;
    const int mpair = wid & 3;        // 32-row pair: slabs mpair*32, +16
    const int nhalf = wid >> 2;       // tiles nhalf*6 .. +5
    const int n0    = blockIdx.x * 128;

    float acc[2][6][4];
    #pragma unroll
    for (int s = 0; s < 2; s++)
        #pragma unroll
        for (int j = 0; j < 6; j++)
            #pragma unroll
            for (int i = 0; i < 4; i++) acc[s][j][i] = 0.f;

    const int a_row = (lane & 15);
    const int a_kh  = ((lane >> 4) & 1) * 8;
    const int b_row = (lane & 7);
    const int b_kh  = ((lane >> 3) & 1) * 8;

    // Preload chunk 0 X values into registers (128 rows x 16 float4)
    float4 xv[8];
    #pragma unroll
    for (int ii = 0; ii < 8; ii++) {
        int q = tid + 256 * ii;
        int r = q >> 4, j4 = q & 15;
        int node = n0 + r;
        xv[ii] = (node < N)
            ? *(const float4*)&X[(size_t)node * IN_DIM + 4 * j4]
            : make_float4(0.f, 0.f, 0.f, 0.f);
    }

    for (int c = 0; c < 4; c++) {
        __syncthreads();   // prev chunk's MMAs done reading A/B

        // Issue B chunk c -> BH/BL (cp.async; overlaps the A stores below)
        for (int i = tid; i < 1728; i += 256) {
            if (i < 864)
                cp16(sb + SM_BH + 16 * i,
                     (const char*)g_Bhp + c * 13824 + 16 * i, 16);
            else
                cp16(sb + SM_BL + 16 * (i - 864),
                     (const char*)g_Blp + c * 13824 + 16 * (i - 864), 16);
        }
        CP_COMMIT();

        // Store staged X (convert to hi/lo bf16)
        #pragma unroll
        for (int ii = 0; ii < 8; ii++) {
            int q = tid + 256 * ii;
            int r = q >> 4, j4 = q & 15;
            float4 v = xv[ii];
            unsigned short hx = bf16h(v.x), hy = bf16h(v.y),
                           hz = bf16h(v.z), hw = bf16h(v.w);
            unsigned short lx = bf16h(v.x - bf16f(hx)), ly = bf16h(v.y - bf16f(hy)),
                           lz = bf16h(v.z - bf16f(hz)), lw = bf16h(v.w - bf16f(hw));
            unsigned byte = r * (ASTRIDE * 2) + 8 * j4;
            *(uint2*)(smem + SM_AH + byte) =
                make_uint2((unsigned)hx | ((unsigned)hy << 16),
                           (unsigned)hz | ((unsigned)hw << 16));
            *(uint2*)(smem + SM_AL + byte) =
                make_uint2((unsigned)lx | ((unsigned)ly << 16),
                           (unsigned)lz | ((unsigned)lw << 16));
        }

        // Prefetch next chunk's X (LDG in flight under the MMA block)
        if (c < 3) {
            #pragma unroll
            for (int ii = 0; ii < 8; ii++) {
                int q = tid + 256 * ii;
                int r = q >> 4, j4 = q & 15;
                int node = n0 + r;
                xv[ii] = (node < N)
                    ? *(const float4*)&X[(size_t)node * IN_DIM + (c + 1) * 64 + 4 * j4]
                    : make_float4(0.f, 0.f, 0.f, 0.f);
            }
        }

        CP_WAIT0();            // B(c) arrived
        __syncthreads();       // A conversions visible

        #pragma unroll
        for (int ks = 0; ks < 4; ks++) {
            // A fragments for BOTH 16-row slabs (B frags reused across them)
            unsigned ah[2][4], al[2][4];
            #pragma unroll
            for (int s = 0; s < 2; s++) {
                unsigned byte = (mpair * 32 + s * 16 + a_row) * (ASTRIDE * 2)
                              + (ks * 16 + a_kh) * 2;
                ldsm_x4(ah[s], sb + SM_AH + byte);
                ldsm_x4(al[s], sb + SM_AL + byte);
            }
            #pragma unroll
            for (int j = 0; j < 6; j++) {
                int jj = nhalf * 6 + j;
                unsigned bh[2], bl[2];
                unsigned byte = (jj * 8 + b_row) * (ASTRIDE * 2)
                              + (ks * 16 + b_kh) * 2;
                ldsm_x2(bh, sb + SM_BH + byte);
                ldsm_x2(bl, sb + SM_BL + byte);
                #pragma unroll
                for (int s = 0; s < 2; s++) {
                    mma_bf16(acc[s][j], ah[s], bh);
                    mma_bf16(acc[s][j], ah[s], bl);
                    mma_bf16(acc[s][j], al[s], bh);
                }
            }
        }
    }

    // Epilogue: Q separate; K/V interleaved per node (64-float row)
    const int g  = lane >> 2;
    const int tt = lane & 3;
    #pragma unroll
    for (int s = 0; s < 2; s++) {
        const int row_hi = n0 + mpair * 32 + s * 16 + g;
        const int row_lo = row_hi + 8;
        #pragma unroll
        for (int j = 0; j < 6; j++) {
            int jj  = nhalf * 6 + j;
            int col = 8 * (jj & 3) + 2 * tt;
            float* p_hi;
            float* p_lo;
            if (jj < 4) {
                p_hi = &g_Q[(size_t)row_hi * HD + col];
                p_lo = &g_Q[(size_t)row_lo * HD + col];
            } else if (jj < 8) {
                p_hi = &g_KV[(size_t)row_hi * 64 + col];
                p_lo = &g_KV[(size_t)row_lo * 64 + col];
            } else {
                p_hi = &g_KV[(size_t)row_hi * 64 + 32 + col];
                p_lo = &g_KV[(size_t)row_lo * 64 + 32 + col];
            }
            if (row_hi < N) *(float2*)p_hi = make_float2(acc[s][j][0], acc[s][j][1]);
            if (row_lo < N) *(float2*)p_lo = make_float2(acc[s][j][2], acc[s][j][3]);
        }
    }
}

// ---------------------------------------------------------------------------
// CSR hist + scan in ONE kernel (grid-barrier; state self-resets).
// ---------------------------------------------------------------------------
__global__ void __launch_bounds__(SCAN_BLK)
csr_kernel(const int* __restrict__ ei, int E, int N, int nb)
{
    __shared__ int wsum[32];
    __shared__ int sh2[128];
    __shared__ int s_boff;

    const int t    = threadIdx.x;
    const int lane = t & 31;
    const int wid  = t >> 5;
    const int b    = blockIdx.x;
    const int gtid = b * SCAN_BLK + t;
    const int gsz  = nb * SCAN_BLK;

    const int nquad = E >> 2;
    for (int q = gtid; q < nquad; q += gsz) {
        int4 s = ((const int4*)ei)[q];
        atomicAdd(&g_cnt[s.x], 1);
        atomicAdd(&g_cnt[s.y], 1);
        atomicAdd(&g_cnt[s.z], 1);
        atomicAdd(&g_cnt[s.w], 1);
    }
    for (int e = (nquad << 2) + gtid; e < E; e += gsz)
        atomicAdd(&g_cnt[ei[e]], 1);

    __syncthreads();
    if (t == 0) {
        __threadfence();
        int ticket = atomicAdd(&g_bar1, 1);
        if (ticket == nb - 1) atomicExch(&g_rel1, 1);
        while (atomicAdd(&g_rel1, 0) == 0) {}
        __threadfence();
    }
    __syncthreads();

    const int i = gtid;
    int v = (i < N) ? g_cnt[i] : 0;
    int x = v;
    #pragma unroll
    for (int off = 1; off < 32; off <<= 1) {
        int y = __shfl_up_sync(0xffffffffu, x, off);
        if (lane >= off) x += y;
    }
    if (lane == 31) wsum[wid] = x;
    __syncthreads();
    if (wid == 0) {
        int s = wsum[lane];
        #pragma unroll
        for (int off = 1; off < 32; off <<= 1) {
            int y = __shfl_up_sync(0xffffffffu, s, off);
            if (lane >= off) s += y;
        }
        wsum[lane] = s;
    }
    __syncthreads();
    const int base = (wid > 0) ? wsum[wid - 1] : 0;
    const int excl = base + x - v;

    if (t == SCAN_BLK - 1) {
        g_bsum[b] = base + x;
        __threadfence();
        atomicExch(&g_ready[b], 1);
    }

    int val = 0;
    if (t < nb) {
        while (atomicAdd(&g_ready[t], 0) == 0) {}
        __threadfence();
        val = g_bsum[t];
    }
    if (t < 128) sh2[t] = (t < nb) ? val : 0;
    __syncthreads();
    #pragma unroll
    for (int off = 1; off < 128; off <<= 1) {
        int y = (t < 128 && t >= off) ? sh2[t - off] : 0;
        __syncthreads();
        if (t < 128) sh2[t] += y;
        __syncthreads();
    }
    if (t == b) s_boff = sh2[b] - val;
    __syncthreads();

    if (i < N) {
        int rp = s_boff + excl;
        g_rowptr[i] = rp;
        g_cursor[i] = rp;
    }

    __syncthreads();
    if (t == 0) {
        int d = atomicAdd(&g_done1, 1);
        if (d == nb - 1) {
            for (int k = 0; k < nb; k++) g_ready[k] = 0;
            g_bar1 = 0;
            g_rel1 = 0;
            g_done1 = 0;
            __threadfence();
        }
    }
}

__global__ void scatter_kernel(const int* __restrict__ ei, int E)
{
    int b = (blockIdx.x * blockDim.x + threadIdx.x) * 4;
    if (b + 3 < E) {
        int4 s = *(const int4*)&ei[b];
        int4 d = *(const int4*)&ei[E + b];
        g_sdst[atomicAdd(&g_cursor[s.x], 1)] = d.x;
        g_sdst[atomicAdd(&g_cursor[s.y], 1)] = d.y;
        g_sdst[atomicAdd(&g_cursor[s.z], 1)] = d.z;
        g_sdst[atomicAdd(&g_cursor[s.w], 1)] = d.w;
    } else {
        for (int e = b; e < E; e++) {
            int s = ei[e];
            int d = ei[E + e];
            g_sdst[atomicAdd(&g_cursor[s], 1)] = d;
        }
    }
}

// ---------------------------------------------------------------------------
// Fused softmax + aggregate (R12, measured 36.6us): FOUR nodes per warp,
// one 8-lane group per node, 2-edge unroll with index prefetch.
// ---------------------------------------------------------------------------
__global__ void __launch_bounds__(256)
agg_kernel(float* __restrict__ out, int N)
{
    const int lane = threadIdx.x & 31;
    const int warp = (blockIdx.x * blockDim.x + threadIdx.x) >> 5;
    const int grp  = lane >> 3;
    const int sub  = lane & 7;
    const int n    = warp * 4 + grp;
    const bool nvalid = (n < N);
    const int nn   = nvalid ? n : 0;

    const float4 q4 = *(const float4*)&g_Q[(size_t)nn * HD + sub * 4];
    const int rs  = g_rowptr[nn];
    const int cnt = nvalid ? g_cnt[nn] : 0;

    int nit = (cnt + 1) >> 1;
    nit = max(nit, __shfl_xor_sync(0xffffffffu, nit, 8));
    nit = max(nit, __shfl_xor_sync(0xffffffffu, nit, 16));

    float4 acc = make_float4(0.f, 0.f, 0.f, 0.f);
    float  sw  = 0.f;

    bool v0 = (0 < cnt);
    bool v1 = (1 < cnt);
    int  d0 = v0 ? g_sdst[rs] : 0;
    int  d1 = v1 ? g_sdst[rs + 1] : 0;

    for (int it = 0; it < nit; it++) {
        float4 k0 = make_float4(0.f, 0.f, 0.f, 0.f), u0 = k0, k1 = k0, u1 = k0;
        if (v0) {
            const float* kv = &g_KV[(size_t)d0 * 64];
            k0 = *(const float4*)&kv[sub * 4];
            u0 = *(const float4*)&kv[32 + sub * 4];
        }
        if (v1) {
            const float* kv = &g_KV[(size_t)d1 * 64];
            k1 = *(const float4*)&kv[sub * 4];
            u1 = *(const float4*)&kv[32 + sub * 4];
        }

        bool nv0 = false, nv1 = false;
        int  nd0 = 0, nd1 = 0;
        {
            int e = (it + 1) * 2;
            nv0 = (e < cnt);
            nv1 = (e + 1 < cnt);
            nd0 = nv0 ? g_sdst[rs + e] : 0;
            nd1 = nv1 ? g_sdst[rs + e + 1] : 0;
        }

        float p0 = q4.x * k0.x + q4.y * k0.y + q4.z * k0.z + q4.w * k0.w;
        float p1 = q4.x * k1.x + q4.y * k1.y + q4.z * k1.z + q4.w * k1.w;
        p0 += __shfl_xor_sync(0xffffffffu, p0, 1);
        p1 += __shfl_xor_sync(0xffffffffu, p1, 1);
        p0 += __shfl_xor_sync(0xffffffffu, p0, 2);
        p1 += __shfl_xor_sync(0xffffffffu, p1, 2);
        p0 += __shfl_xor_sync(0xffffffffu, p0, 4);
        p1 += __shfl_xor_sync(0xffffffffu, p1, 4);

        float w0 = v0 ? __expf(p0 * 0.17677669529663687f) : 0.f;
        float w1 = v1 ? __expf(p1 * 0.17677669529663687f) : 0.f;
        sw += w0 + w1;

        acc.x += w0 * u0.x + w1 * u1.x;
        acc.y += w0 * u0.y + w1 * u1.y;
        acc.z += w0 * u0.z + w1 * u1.z;
        acc.w += w0 * u0.w + w1 * u1.w;

        v0 = nv0; v1 = nv1; d0 = nd0; d1 = nd1;
    }

    if (nvalid) {
        if (sub == 0) g_cnt[n] = 0;
        float inv = (sw > 0.f) ? (1.f / sw) : 0.f;
        float4 o = make_float4(acc.x * inv, acc.y * inv, acc.z * inv, acc.w * inv);
        *(float4*)&out[(size_t)n * HD + sub * 4] = o;
    }
}

// ---------------------------------------------------------------------------
// Launch: 5 kernels, fork-join across two streams.
//   csr(1,s0)  scatter(2,s0)  bprep(3,s1)  qkv(4,s1 <- profiled)  agg(5,s0)
// ---------------------------------------------------------------------------
extern "C" void kernel_launch(void* const* d_in, const int* in_sizes, int n_in,
                              void* d_out, int out_size)
{
    const float* X  = (const float*)d_in[0];
    const int*   ei = (const int*)d_in[1];     // int32 edge indices
    const float* Wq = (const float*)d_in[2];
    const float* Wk = (const float*)d_in[3];
    const float* Wv = (const float*)d_in[4];
    float* out = (float*)d_out;

    const int N = in_sizes[0] / IN_DIM;
    const int E = in_sizes[1] / 2;
    const int nb = (N + SCAN_BLK - 1) / SCAN_BLK;

    static cudaStream_t s1 = nullptr;
    static cudaEvent_t  evF = nullptr, evA = nullptr;
    if (!s1) {
        cudaFuncSetAttribute(qkv_mma_kernel,
                             cudaFuncAttributeMaxDynamicSharedMemorySize,
                             QKV_SMEM);
        cudaStreamCreateWithFlags(&s1, cudaStreamNonBlocking);
        cudaEventCreateWithFlags(&evF, cudaEventDisableTiming);
        cudaEventCreateWithFlags(&evA, cudaEventDisableTiming);
    }

    // Fork
    cudaEventRecord(evF, 0);
    cudaStreamWaitEvent(s1, evF, 0);

    csr_kernel<<<nb, SCAN_BLK>>>(ei, E, N, nb);                        // 1
    scatter_kernel<<<(E / 4 + 255) / 256, 256>>>(ei, E);               // 2
    bprep_kernel<<<48, 256, 0, s1>>>(Wq, Wk, Wv);                      // 3
    qkv_mma_kernel<<<(N + 127) / 128, 256, QKV_SMEM, s1>>>(X, N);      // 4 <- profiled
    cudaEventRecord(evA, s1);

    // Join
    cudaStreamWaitEvent(0, evA, 0);
    agg_kernel<<<((N * 8) + 255) / 256, 256>>>(out, N);                // 5
}